// round 5
// baseline (speedup 1.0000x reference)
#include <cuda_runtime.h>
#include <math.h>

#define T_TOK 2048
#define HDIM  2048
#define IDIM  7168
#define NEXP  8
#define RDIM  64
#define SLOTS (2 * T_TOK)
#define SCALE 0.25f

// ---------------- scratch (static device arrays; no allocation) ----------------
__device__ float g_base_gate[(size_t)T_TOK * IDIM];
__device__ float g_base_up  [(size_t)T_TOK * IDIM];
__device__ float g_hbar     [(size_t)T_TOK * IDIM];
__device__ float g_hid      [(size_t)SLOTS * IDIM];   // hid per (token,k) slot
__device__ float g_dl       [(size_t)SLOTS * HDIM];   // down-LoRA per slot
__device__ float g_tg [SLOTS * RDIM];
__device__ float g_tu [SLOTS * RDIM];
__device__ float g_tdw[SLOTS * RDIM];
__device__ float g_w  [SLOTS];
__device__ int   g_cnt[NEXP];
__device__ int   g_list[NEXP][SLOTS];

__device__ __forceinline__ float warpsum(float v) {
    #pragma unroll
    for (int o = 16; o > 0; o >>= 1) v += __shfl_down_sync(0xffffffffu, v, o);
    return v;
}

// ---------------- cp.async helpers ----------------
__device__ __forceinline__ void cp16(void* smem_dst, const void* gsrc) {
    unsigned saddr = (unsigned)__cvta_generic_to_shared(smem_dst);
    asm volatile("cp.async.cg.shared.global [%0], [%1], 16;" :: "r"(saddr), "l"(gsrc));
}
__device__ __forceinline__ void cp_commit() {
    asm volatile("cp.async.commit_group;");
}
__device__ __forceinline__ void cp_wait0() {
    asm volatile("cp.async.wait_group 0;");
}

// ---------------- 0. zero expert counters ----------------
__global__ void zero_cnt_kernel() {
    if (threadIdx.x < NEXP) g_cnt[threadIdx.x] = 0;
}

// ---------------- 1. routing: conf -> bids -> top2 -> softmax -> lists ----------------
__global__ void routing_kernel(const float* __restrict__ x,
                               const float* __restrict__ cw,
                               const float* __restrict__ cb,
                               const float* __restrict__ wealth) {
    int t = blockIdx.x, tid = threadIdx.x;
    const float* xt = x + (size_t)t * HDIM;
    float acc[NEXP];
    #pragma unroll
    for (int e = 0; e < NEXP; e++) acc[e] = 0.f;
    for (int h = tid; h < HDIM; h += 256) {
        float xv = xt[h];
        #pragma unroll
        for (int e = 0; e < NEXP; e++) acc[e] += xv * cw[(size_t)e * HDIM + h];
    }
    __shared__ float part[8][NEXP];
    int warp = tid >> 5, lane = tid & 31;
    #pragma unroll
    for (int e = 0; e < NEXP; e++) acc[e] = warpsum(acc[e]);
    if (lane == 0) {
        #pragma unroll
        for (int e = 0; e < NEXP; e++) part[warp][e] = acc[e];
    }
    __syncthreads();
    if (tid == 0) {
        float bids[NEXP];
        #pragma unroll
        for (int e = 0; e < NEXP; e++) {
            float s = 0.f;
            #pragma unroll
            for (int w = 0; w < 8; w++) s += part[w][e];
            float conf = 1.f / (1.f + expf(-(s + cb[e])));
            bids[e] = conf * wealth[e];
        }
        int i0 = 0, i1 = -1;
        float b0 = bids[0], b1 = -1e30f;
        #pragma unroll
        for (int e = 1; e < NEXP; e++) {
            if (bids[e] > b0)      { b1 = b0; i1 = i0; b0 = bids[e]; i0 = e; }
            else if (bids[e] > b1) { b1 = bids[e]; i1 = e; }
        }
        float e1 = expf(b1 - b0);
        float inv = 1.f / (1.f + e1);
        g_w[t * 2 + 0] = inv;
        g_w[t * 2 + 1] = e1 * inv;
        int p0 = atomicAdd(&g_cnt[i0], 1); g_list[i0][p0] = t * 2 + 0;
        int p1 = atomicAdd(&g_cnt[i1], 1); g_list[i1][p1] = t * 2 + 1;
    }
}

// ---------------- 2. grouped LoRA-in: tg/tu[slot] = x_t @ {g,u}A_e^T ----------------
// grid (SLOTS/64, NEXP); block 256. 64 slots x 64 r, K = HDIM in chunks of 16.
__global__ void __launch_bounds__(256) lora_in_grouped(const float* __restrict__ x,
                                                       const float* __restrict__ gA,
                                                       const float* __restrict__ uA) {
    int e = blockIdx.y;
    int cnt = g_cnt[e];
    int base = blockIdx.x * 64;
    if (base >= cnt) return;
    __shared__ float xsT [16][64];   // [k][tok]
    __shared__ float gAsT[16][64];   // [k][r]
    __shared__ float uAsT[16][64];
    __shared__ int sidx[64];
    int tid = threadIdx.x;
    if (tid < 64) sidx[tid] = (base + tid < cnt) ? g_list[e][base + tid] : -1;
    __syncthreads();

    int ld_row = tid >> 2;            // 0..63
    int ld_k   = (tid & 3) * 4;       // 0,4,8,12
    int s_ld = sidx[ld_row];
    int t_ld = (s_ld >= 0) ? (s_ld >> 1) : 0;
    const float* xp  = x  + (size_t)t_ld * HDIM + ld_k;
    const float* gAp = gA + ((size_t)e * RDIM + ld_row) * HDIM + ld_k;
    const float* uAp = uA + ((size_t)e * RDIM + ld_row) * HDIM + ld_k;

    int tx = tid & 15, ty = tid >> 4;
    float accg[4][4], accu[4][4];
    #pragma unroll
    for (int i = 0; i < 4; i++)
        #pragma unroll
        for (int j = 0; j < 4; j++) { accg[i][j] = 0.f; accu[i][j] = 0.f; }

    for (int k0 = 0; k0 < HDIM; k0 += 16) {
        float4 xv = *(const float4*)(xp + k0);
        float4 gv = *(const float4*)(gAp + k0);
        float4 uv = *(const float4*)(uAp + k0);
        xsT [ld_k + 0][ld_row] = xv.x; xsT [ld_k + 1][ld_row] = xv.y;
        xsT [ld_k + 2][ld_row] = xv.z; xsT [ld_k + 3][ld_row] = xv.w;
        gAsT[ld_k + 0][ld_row] = gv.x; gAsT[ld_k + 1][ld_row] = gv.y;
        gAsT[ld_k + 2][ld_row] = gv.z; gAsT[ld_k + 3][ld_row] = gv.w;
        uAsT[ld_k + 0][ld_row] = uv.x; uAsT[ld_k + 1][ld_row] = uv.y;
        uAsT[ld_k + 2][ld_row] = uv.z; uAsT[ld_k + 3][ld_row] = uv.w;
        __syncthreads();
        #pragma unroll
        for (int k = 0; k < 16; k++) {
            float a0 = xsT[k][ty * 4 + 0], a1 = xsT[k][ty * 4 + 1];
            float a2 = xsT[k][ty * 4 + 2], a3 = xsT[k][ty * 4 + 3];
            float4 gr = *(const float4*)&gAsT[k][tx * 4];
            float4 ur = *(const float4*)&uAsT[k][tx * 4];
            accg[0][0] += a0 * gr.x; accg[0][1] += a0 * gr.y; accg[0][2] += a0 * gr.z; accg[0][3] += a0 * gr.w;
            accg[1][0] += a1 * gr.x; accg[1][1] += a1 * gr.y; accg[1][2] += a1 * gr.z; accg[1][3] += a1 * gr.w;
            accg[2][0] += a2 * gr.x; accg[2][1] += a2 * gr.y; accg[2][2] += a2 * gr.z; accg[2][3] += a2 * gr.w;
            accg[3][0] += a3 * gr.x; accg[3][1] += a3 * gr.y; accg[3][2] += a3 * gr.z; accg[3][3] += a3 * gr.w;
            accu[0][0] += a0 * ur.x; accu[0][1] += a0 * ur.y; accu[0][2] += a0 * ur.z; accu[0][3] += a0 * ur.w;
            accu[1][0] += a1 * ur.x; accu[1][1] += a1 * ur.y; accu[1][2] += a1 * ur.z; accu[1][3] += a1 * ur.w;
            accu[2][0] += a2 * ur.x; accu[2][1] += a2 * ur.y; accu[2][2] += a2 * ur.z; accu[2][3] += a2 * ur.w;
            accu[3][0] += a3 * ur.x; accu[3][1] += a3 * ur.y; accu[3][2] += a3 * ur.z; accu[3][3] += a3 * ur.w;
        }
        __syncthreads();
    }
    #pragma unroll
    for (int tt = 0; tt < 4; tt++) {
        int s = sidx[ty * 4 + tt];
        if (s < 0) continue;
        *(float4*)&g_tg[(size_t)s * RDIM + tx * 4] = make_float4(accg[tt][0], accg[tt][1], accg[tt][2], accg[tt][3]);
        *(float4*)&g_tu[(size_t)s * RDIM + tx * 4] = make_float4(accu[tt][0], accu[tt][1], accu[tt][2], accu[tt][3]);
    }
}

// ---------------- split-tf32 helpers ----------------
__device__ __forceinline__ unsigned f2tf32(float x) {
    unsigned r;
    asm("cvt.rna.tf32.f32 %0, %1;" : "=r"(r) : "f"(x));
    return r;
}
__device__ __forceinline__ void split_tf32(float x, unsigned& hi, unsigned& lo) {
    hi = f2tf32(x);
    lo = f2tf32(x - __uint_as_float(hi));
}
__device__ __forceinline__ void mma_tf32(float& c0, float& c1, float& c2, float& c3,
                                         unsigned a0, unsigned a1, unsigned a2, unsigned a3,
                                         unsigned b0, unsigned b1) {
    asm volatile(
        "mma.sync.aligned.m16n8k8.row.col.f32.tf32.tf32.f32 "
        "{%0,%1,%2,%3}, {%4,%5,%6,%7}, {%8,%9}, {%0,%1,%2,%3};\n"
        : "+f"(c0), "+f"(c1), "+f"(c2), "+f"(c3)
        : "r"(a0), "r"(a1), "r"(a2), "r"(a3), "r"(b0), "r"(b1));
}

// ---------------- tf32 tensor-core GEMM: C[M,N] = A[M,K] @ B[N,K]^T ----------------
// BM=BN=128, BK=16, 256 threads, warp grid 2(m) x 4(n), warp tile 64x32.
// cp.async double-buffered smem; split-tf32 3-pass for fp32-grade accuracy.
__device__ __forceinline__ void gemm_tf32_body(const float* __restrict__ A,
                                               const float* __restrict__ B,
                                               float* __restrict__ C,
                                               int N, int K) {
    __shared__ float As[2][128][20];   // row stride 80B (16B-aligned); frag loads conflict-free
    __shared__ float Bs[2][128][20];

    int tid = threadIdx.x;
    int m0 = blockIdx.y * 128, n0 = blockIdx.x * 128;
    int warp = tid >> 5, lane = tid & 31;
    int wm = (warp & 1) * 64;
    int wn = (warp >> 1) * 32;
    int g = lane >> 2, tq = lane & 3;

    int lrow = tid >> 1;
    int lcol = (tid & 1) * 8;
    const float* Ap = A + (size_t)(m0 + lrow) * K + lcol;
    const float* Bp = B + (size_t)(n0 + lrow) * K + lcol;

    float acc[4][4][4];
    #pragma unroll
    for (int mi = 0; mi < 4; mi++)
        #pragma unroll
        for (int ni = 0; ni < 4; ni++)
            #pragma unroll
            for (int c = 0; c < 4; c++) acc[mi][ni][c] = 0.f;

    int nk = K >> 4;

    // preload tile 0 (async)
    cp16(&As[0][lrow][lcol],     Ap);
    cp16(&As[0][lrow][lcol + 4], Ap + 4);
    cp16(&Bs[0][lrow][lcol],     Bp);
    cp16(&Bs[0][lrow][lcol + 4], Bp + 4);
    cp_commit();
    cp_wait0();
    __syncthreads();

    for (int kt = 0; kt < nk; kt++) {
        int cur = kt & 1;
        if (kt + 1 < nk) {
            int nxt = cur ^ 1;
            int k0 = (kt + 1) << 4;
            cp16(&As[nxt][lrow][lcol],     Ap + k0);
            cp16(&As[nxt][lrow][lcol + 4], Ap + k0 + 4);
            cp16(&Bs[nxt][lrow][lcol],     Bp + k0);
            cp16(&Bs[nxt][lrow][lcol + 4], Bp + k0 + 4);
            cp_commit();
        }
        #pragma unroll
        for (int ks = 0; ks < 2; ks++) {
            int k0 = ks * 8;
            unsigned ahi[4][4], alo[4][4];
            #pragma unroll
            for (int mi = 0; mi < 4; mi++) {
                int mb = wm + mi * 16;
                float f0 = As[cur][mb + g][k0 + tq];
                float f1 = As[cur][mb + g + 8][k0 + tq];
                float f2 = As[cur][mb + g][k0 + tq + 4];
                float f3 = As[cur][mb + g + 8][k0 + tq + 4];
                split_tf32(f0, ahi[mi][0], alo[mi][0]);
                split_tf32(f1, ahi[mi][1], alo[mi][1]);
                split_tf32(f2, ahi[mi][2], alo[mi][2]);
                split_tf32(f3, ahi[mi][3], alo[mi][3]);
            }
            unsigned bhi[4][2], blo[4][2];
            #pragma unroll
            for (int ni = 0; ni < 4; ni++) {
                int nb = wn + ni * 8;
                float f0 = Bs[cur][nb + g][k0 + tq];
                float f1 = Bs[cur][nb + g][k0 + tq + 4];
                split_tf32(f0, bhi[ni][0], blo[ni][0]);
                split_tf32(f1, bhi[ni][1], blo[ni][1]);
            }
            #pragma unroll
            for (int mi = 0; mi < 4; mi++)
                #pragma unroll
                for (int ni = 0; ni < 4; ni++) {
                    float* c = acc[mi][ni];
                    mma_tf32(c[0], c[1], c[2], c[3],
                             ahi[mi][0], ahi[mi][1], ahi[mi][2], ahi[mi][3],
                             bhi[ni][0], bhi[ni][1]);
                    mma_tf32(c[0], c[1], c[2], c[3],
                             ahi[mi][0], ahi[mi][1], ahi[mi][2], ahi[mi][3],
                             blo[ni][0], blo[ni][1]);
                    mma_tf32(c[0], c[1], c[2], c[3],
                             alo[mi][0], alo[mi][1], alo[mi][2], alo[mi][3],
                             bhi[ni][0], bhi[ni][1]);
                }
        }
        cp_wait0();
        __syncthreads();
    }
    #pragma unroll
    for (int mi = 0; mi < 4; mi++) {
        int row0 = m0 + wm + mi * 16 + g;
        int row1 = row0 + 8;
        #pragma unroll
        for (int ni = 0; ni < 4; ni++) {
            int col = n0 + wn + ni * 8 + 2 * tq;
            float* c = acc[mi][ni];
            *(float2*)&C[(size_t)row0 * N + col] = make_float2(c[0], c[1]);
            *(float2*)&C[(size_t)row1 * N + col] = make_float2(c[2], c[3]);
        }
    }
}

// ---------------- 3. base gate/up GEMM ----------------
__global__ void __launch_bounds__(256, 1) sgemm_gateup(const float* __restrict__ x,
                             const float* __restrict__ Wg,
                             const float* __restrict__ Wu) {
    const float* B = blockIdx.z ? Wu : Wg;
    float* C = blockIdx.z ? g_base_up : g_base_gate;
    gemm_tf32_body(x, B, C, IDIM, HDIM);
}

// ---------------- 4. grouped hid: hid[slot][i] = silu(gate)*up ----------------
// grid (IDIM/64, NEXP); gB/uB tile staged once per block; token chunks of 32.
__global__ void __launch_bounds__(256) hid_grouped(const float* __restrict__ gB,
                                                   const float* __restrict__ uB) {
    int e = blockIdx.y;
    int cnt = g_cnt[e];
    if (cnt == 0) return;
    int i0 = blockIdx.x * 64;
    __shared__ float gBsT[RDIM][64];   // [r][i]
    __shared__ float uBsT[RDIM][64];
    __shared__ float tgsT[RDIM][32];   // [r][tok]
    __shared__ float tusT[RDIM][32];
    int tid = threadIdx.x;

    // stage gB/uB tile (transposed)
    {
        int il = tid >> 2, rb = (tid & 3) * 4;
        const float* gp = gB + ((size_t)e * IDIM + i0 + il) * RDIM;
        const float* up = uB + ((size_t)e * IDIM + i0 + il) * RDIM;
        #pragma unroll
        for (int j = 0; j < 4; j++) {
            int r0 = rb + j * 16;
            float4 gv = *(const float4*)(gp + r0);
            float4 uv = *(const float4*)(up + r0);
            gBsT[r0 + 0][il] = gv.x; gBsT[r0 + 1][il] = gv.y; gBsT[r0 + 2][il] = gv.z; gBsT[r0 + 3][il] = gv.w;
            uBsT[r0 + 0][il] = uv.x; uBsT[r0 + 1][il] = uv.y; uBsT[r0 + 2][il] = uv.z; uBsT[r0 + 3][il] = uv.w;
        }
    }
    __syncthreads();

    int tx = tid & 15, ty = tid >> 4;
    int tl_ld = tid >> 3;              // 0..31 (token for tg/tu loads)
    int rb_ld = (tid & 7) * 8;

    for (int c0 = 0; c0 < cnt; c0 += 32) {
        int s_ld = (c0 + tl_ld < cnt) ? g_list[e][c0 + tl_ld] : 0;
        #pragma unroll
        for (int h = 0; h < 2; h++) {
            int r0 = rb_ld + h * 4;
            float4 gv = *(const float4*)&g_tg[(size_t)s_ld * RDIM + r0];
            float4 uv = *(const float4*)&g_tu[(size_t)s_ld * RDIM + r0];
            tgsT[r0 + 0][tl_ld] = gv.x; tgsT[r0 + 1][tl_ld] = gv.y; tgsT[r0 + 2][tl_ld] = gv.z; tgsT[r0 + 3][tl_ld] = gv.w;
            tusT[r0 + 0][tl_ld] = uv.x; tusT[r0 + 1][tl_ld] = uv.y; tusT[r0 + 2][tl_ld] = uv.z; tusT[r0 + 3][tl_ld] = uv.w;
        }
        __syncthreads();

        float accg[2][4], accu[2][4];
        #pragma unroll
        for (int i = 0; i < 2; i++)
            #pragma unroll
            for (int j = 0; j < 4; j++) { accg[i][j] = 0.f; accu[i][j] = 0.f; }
        #pragma unroll
        for (int r = 0; r < RDIM; r++) {
            float g0 = tgsT[r][ty * 2 + 0], g1 = tgsT[r][ty * 2 + 1];
            float u0 = tusT[r][ty * 2 + 0], u1 = tusT[r][ty * 2 + 1];
            float4 gb = *(const float4*)&gBsT[r][tx * 4];
            float4 ub = *(const float4*)&uBsT[r][tx * 4];
            accg[0][0] += g0 * gb.x; accg[0][1] += g0 * gb.y; accg[0][2] += g0 * gb.z; accg[0][3] += g0 * gb.w;
            accg[1][0] += g1 * gb.x; accg[1][1] += g1 * gb.y; accg[1][2] += g1 * gb.z; accg[1][3] += g1 * gb.w;
            accu[0][0] += u0 * ub.x; accu[0][1] += u0 * ub.y; accu[0][2] += u0 * ub.z; accu[0][3] += u0 * ub.w;
            accu[1][0] += u1 * ub.x; accu[1][1] += u1 * ub.y; accu[1][2] += u1 * ub.z; accu[1][3] += u1 * ub.w;
        }
        #pragma unroll
        for (int tt = 0; tt < 2; tt++) {
            int tl = ty * 2 + tt;
            if (c0 + tl >= cnt) continue;
            int s = g_list[e][c0 + tl];
            int t = s >> 1;
            size_t boff = (size_t)t * IDIM + i0 + tx * 4;
            float4 bg = *(const float4*)&g_base_gate[boff];
            float4 bu = *(const float4*)&g_base_up[boff];
            float gte[4] = {bg.x + SCALE * accg[tt][0], bg.y + SCALE * accg[tt][1],
                            bg.z + SCALE * accg[tt][2], bg.w + SCALE * accg[tt][3]};
            float upe[4] = {bu.x + SCALE * accu[tt][0], bu.y + SCALE * accu[tt][1],
                            bu.z + SCALE * accu[tt][2], bu.w + SCALE * accu[tt][3]};
            float4 hv;
            hv.x = gte[0] / (1.f + expf(-gte[0])) * upe[0];
            hv.y = gte[1] / (1.f + expf(-gte[1])) * upe[1];
            hv.z = gte[2] / (1.f + expf(-gte[2])) * upe[2];
            hv.w = gte[3] / (1.f + expf(-gte[3])) * upe[3];
            *(float4*)&g_hid[(size_t)s * IDIM + i0 + tx * 4] = hv;
        }
        __syncthreads();
    }
}

// ---------------- 5. hbar[t] = w0*hid[2t] + w1*hid[2t+1] ----------------
__global__ void hbar_kernel() {
    int t = blockIdx.x, tid = threadIdx.x;
    float w0 = g_w[t * 2], w1 = g_w[t * 2 + 1];
    const float* h0 = g_hid + (size_t)(t * 2) * IDIM;
    const float* h1 = g_hid + (size_t)(t * 2 + 1) * IDIM;
    float* hb = g_hbar + (size_t)t * IDIM;
    for (int i = tid * 4; i < IDIM; i += 1024) {
        float4 a = *(const float4*)(h0 + i);
        float4 b = *(const float4*)(h1 + i);
        *(float4*)(hb + i) = make_float4(w0 * a.x + w1 * b.x, w0 * a.y + w1 * b.y,
                                         w0 * a.z + w1 * b.z, w0 * a.w + w1 * b.w);
    }
}

// ---------------- 6. grouped td: tdw[slot] = SCALE*w * (hid[slot] @ dA_e^T) ----------------
__global__ void __launch_bounds__(256) td_grouped(const float* __restrict__ dA) {
    int e = blockIdx.y;
    int cnt = g_cnt[e];
    int base = blockIdx.x * 64;
    if (base >= cnt) return;
    __shared__ float hidT[32][64];   // [i][tok]
    __shared__ float dAT [32][64];   // [i][r]
    __shared__ int sidx[64];
    int tid = threadIdx.x;
    if (tid < 64) sidx[tid] = (base + tid < cnt) ? g_list[e][base + tid] : -1;
    __syncthreads();

    int rl = tid >> 2;
    int ib = (tid & 3) * 8;
    int s_ld = sidx[rl];
    const float* hp = g_hid + (size_t)(s_ld >= 0 ? s_ld : 0) * IDIM + ib;
    const float* dp = dA + ((size_t)e * RDIM + rl) * IDIM + ib;

    int tx = tid & 15, ty = tid >> 4;
    float acc[4][4];
    #pragma unroll
    for (int i = 0; i < 4; i++)
        #pragma unroll
        for (int j = 0; j < 4; j++) acc[i][j] = 0.f;

    for (int k0 = 0; k0 < IDIM; k0 += 32) {
        #pragma unroll
        for (int h = 0; h < 2; h++) {
            int i1 = ib + h * 4;
            float4 hv = *(const float4*)(hp + k0 + h * 4);
            float4 dv = *(const float4*)(dp + k0 + h * 4);
            hidT[i1 + 0][rl] = hv.x; hidT[i1 + 1][rl] = hv.y; hidT[i1 + 2][rl] = hv.z; hidT[i1 + 3][rl] = hv.w;
            dAT [i1 + 0][rl] = dv.x; dAT [i1 + 1][rl] = dv.y; dAT [i1 + 2][rl] = dv.z; dAT [i1 + 3][rl] = dv.w;
        }
        __syncthreads();
        #pragma unroll
        for (int i = 0; i < 32; i++) {
            float a0 = hidT[i][ty * 4 + 0], a1 = hidT[i][ty * 4 + 1];
            float a2 = hidT[i][ty * 4 + 2], a3 = hidT[i][ty * 4 + 3];
            float4 d = *(const float4*)&dAT[i][tx * 4];
            acc[0][0] += a0 * d.x; acc[0][1] += a0 * d.y; acc[0][2] += a0 * d.z; acc[0][3] += a0 * d.w;
            acc[1][0] += a1 * d.x; acc[1][1] += a1 * d.y; acc[1][2] += a1 * d.z; acc[1][3] += a1 * d.w;
            acc[2][0] += a2 * d.x; acc[2][1] += a2 * d.y; acc[2][2] += a2 * d.z; acc[2][3] += a2 * d.w;
            acc[3][0] += a3 * d.x; acc[3][1] += a3 * d.y; acc[3][2] += a3 * d.z; acc[3][3] += a3 * d.w;
        }
        __syncthreads();
    }
    #pragma unroll
    for (int tt = 0; tt < 4; tt++) {
        int s = sidx[ty * 4 + tt];
        if (s < 0) continue;
        float wk = g_w[s] * SCALE;
        *(float4*)&g_tdw[(size_t)s * RDIM + tx * 4] =
            make_float4(acc[tt][0] * wk, acc[tt][1] * wk, acc[tt][2] * wk, acc[tt][3] * wk);
    }
}

// ---------------- 7. out = hbar @ D^T ----------------
__global__ void __launch_bounds__(256, 1) sgemm_down(const float* __restrict__ Wd, float* __restrict__ out) {
    gemm_tf32_body(g_hbar, Wd, out, HDIM, IDIM);
}

// ---------------- 8. grouped down-LoRA: dl[slot][h] = tdw[slot] @ dB_e^T ----------------
__global__ void __launch_bounds__(256) downlora_grouped(const float* __restrict__ dB) {
    int e = blockIdx.y;
    int cnt = g_cnt[e];
    if (cnt == 0) return;
    int h0 = blockIdx.x * 64;
    __shared__ float dBT[RDIM][64];   // [r][h]
    __shared__ float tdT[RDIM][64];   // [r][tok]
    __shared__ int sidx[64];
    int tid = threadIdx.x;
    {
        int hl = tid >> 2, rb = (tid & 3) * 4;
        const float* dp = dB + ((size_t)e * HDIM + h0 + hl) * RDIM;
        #pragma unroll
        for (int j = 0; j < 4; j++) {
            int r0 = rb + j * 16;
            float4 v = *(const float4*)(dp + r0);
            dBT[r0 + 0][hl] = v.x; dBT[r0 + 1][hl] = v.y; dBT[r0 + 2][hl] = v.z; dBT[r0 + 3][hl] = v.w;
        }
    }
    __syncthreads();

    int tx = tid & 15, ty = tid >> 4;
    int tl_ld = tid >> 2, rb_ld = (tid & 3) * 4;

    for (int c0 = 0; c0 < cnt; c0 += 64) {
        if (tid < 64) sidx[tid] = (c0 + tid < cnt) ? g_list[e][c0 + tid] : -1;
        __syncthreads();
        int s_ld = sidx[tl_ld];
        const float* tp = g_tdw + (size_t)(s_ld >= 0 ? s_ld : 0) * RDIM;
        #pragma unroll
        for (int j = 0; j < 4; j++) {
            int r0 = rb_ld + j * 16;
            float4 v = *(const float4*)(tp + r0);
            tdT[r0 + 0][tl_ld] = v.x; tdT[r0 + 1][tl_ld] = v.y; tdT[r0 + 2][tl_ld] = v.z; tdT[r0 + 3][tl_ld] = v.w;
        }
        __syncthreads();

        float acc[4][4];
        #pragma unroll
        for (int i = 0; i < 4; i++)
            #pragma unroll
            for (int j = 0; j < 4; j++) acc[i][j] = 0.f;
        #pragma unroll
        for (int r = 0; r < RDIM; r++) {
            float a0 = tdT[r][ty * 4 + 0], a1 = tdT[r][ty * 4 + 1];
            float a2 = tdT[r][ty * 4 + 2], a3 = tdT[r][ty * 4 + 3];
            float4 b = *(const float4*)&dBT[r][tx * 4];
            acc[0][0] += a0 * b.x; acc[0][1] += a0 * b.y; acc[0][2] += a0 * b.z; acc[0][3] += a0 * b.w;
            acc[1][0] += a1 * b.x; acc[1][1] += a1 * b.y; acc[1][2] += a1 * b.z; acc[1][3] += a1 * b.w;
            acc[2][0] += a2 * b.x; acc[2][1] += a2 * b.y; acc[2][2] += a2 * b.z; acc[2][3] += a2 * b.w;
            acc[3][0] += a3 * b.x; acc[3][1] += a3 * b.y; acc[3][2] += a3 * b.z; acc[3][3] += a3 * b.w;
        }
        #pragma unroll
        for (int tt = 0; tt < 4; tt++) {
            int s = sidx[ty * 4 + tt];
            if (s < 0) continue;
            *(float4*)&g_dl[(size_t)s * HDIM + h0 + tx * 4] =
                make_float4(acc[tt][0], acc[tt][1], acc[tt][2], acc[tt][3]);
        }
        __syncthreads();
    }
}

// ---------------- 9. combine: out += dl[2t] + dl[2t+1] ----------------
__global__ void combine_kernel(float* __restrict__ out) {
    int t = blockIdx.x, tid = threadIdx.x;
    const float* d0 = g_dl + (size_t)(t * 2) * HDIM;
    const float* d1 = g_dl + (size_t)(t * 2 + 1) * HDIM;
    float* op = out + (size_t)t * HDIM;
    for (int h = tid * 4; h < HDIM; h += 1024) {
        float4 o = *(const float4*)(op + h);
        float4 a = *(const float4*)(d0 + h);
        float4 b = *(const float4*)(d1 + h);
        *(float4*)(op + h) = make_float4(o.x + a.x + b.x, o.y + a.y + b.y,
                                         o.z + a.z + b.z, o.w + a.w + b.w);
    }
}

// ---------------- launch ----------------
extern "C" void kernel_launch(void* const* d_in, const int* in_sizes, int n_in,
                              void* d_out, int out_size) {
    const float* x      = (const float*)d_in[0];
    const float* conf_w = (const float*)d_in[1];
    const float* conf_b = (const float*)d_in[2];
    const float* wealth = (const float*)d_in[3];
    const float* bgw    = (const float*)d_in[4];
    const float* buw    = (const float*)d_in[5];
    const float* bdw    = (const float*)d_in[6];
    const float* gA     = (const float*)d_in[7];
    const float* gB     = (const float*)d_in[8];
    const float* uA     = (const float*)d_in[9];
    const float* uB     = (const float*)d_in[10];
    const float* dA     = (const float*)d_in[11];
    const float* dB     = (const float*)d_in[12];
    float* out = (float*)d_out;

    zero_cnt_kernel<<<1, 32>>>();
    routing_kernel<<<T_TOK, 256>>>(x, conf_w, conf_b, wealth);
    sgemm_gateup<<<dim3(IDIM / 128, T_TOK / 128, 2), 256>>>(x, bgw, buw);
    lora_in_grouped<<<dim3(SLOTS / 64, NEXP), 256>>>(x, gA, uA);
    hid_grouped<<<dim3(IDIM / 64, NEXP), 256>>>(gB, uB);
    hbar_kernel<<<T_TOK, 256>>>();
    td_grouped<<<dim3(SLOTS / 64, NEXP), 256>>>(dA);
    sgemm_down<<<dim3(HDIM / 128, T_TOK / 128), 256>>>(bdw, out);
    downlora_grouped<<<dim3(HDIM / 64, NEXP), 256>>>(dB);
    combine_kernel<<<T_TOK, 256>>>(out);
}

// round 6
// speedup vs baseline: 1.1758x; 1.1758x over previous
#include <cuda_runtime.h>
#include <cuda_bf16.h>
#include <math.h>

#define T_TOK 2048
#define HDIM  2048
#define IDIM  7168
#define NEXP  8
#define RDIM  64
#define SLOTS (2 * T_TOK)
#define SCALE 0.25f
#define LK_CH 4              // lora_in K chunks
#define TD_CH 8              // td K chunks

// ---------------- scratch (static device arrays; no allocation) ----------------
__device__ float g_base_gate[(size_t)T_TOK * IDIM];
__device__ float g_base_up  [(size_t)T_TOK * IDIM];
__device__ float g_hid      [(size_t)SLOTS * IDIM];
__device__ float g_dl       [(size_t)SLOTS * HDIM];
__device__ float g_tg [SLOTS * RDIM];
__device__ float g_tu [SLOTS * RDIM];
__device__ float g_tdw[SLOTS * RDIM];
__device__ float g_tgp[(size_t)LK_CH * SLOTS * RDIM];
__device__ float g_tup[(size_t)LK_CH * SLOTS * RDIM];
__device__ float g_tdp[(size_t)TD_CH * SLOTS * RDIM];
__device__ float g_w  [SLOTS];
__device__ int   g_cnt[NEXP];
__device__ int   g_list[NEXP][SLOTS];

// packed bf16x2 hi/lo decompositions (pair = 2 consecutive K elements)
__device__ unsigned g_xhi [(size_t)T_TOK * HDIM / 2];
__device__ unsigned g_xlo [(size_t)T_TOK * HDIM / 2];
__device__ unsigned g_wghi[(size_t)IDIM * HDIM / 2];
__device__ unsigned g_wglo[(size_t)IDIM * HDIM / 2];
__device__ unsigned g_wuhi[(size_t)IDIM * HDIM / 2];
__device__ unsigned g_wulo[(size_t)IDIM * HDIM / 2];
__device__ unsigned g_wdhi[(size_t)HDIM * IDIM / 2];
__device__ unsigned g_wdlo[(size_t)HDIM * IDIM / 2];
__device__ unsigned g_hbhi[(size_t)T_TOK * IDIM / 2];
__device__ unsigned g_hblo[(size_t)T_TOK * IDIM / 2];

__device__ __forceinline__ float warpsum(float v) {
    #pragma unroll
    for (int o = 16; o > 0; o >>= 1) v += __shfl_down_sync(0xffffffffu, v, o);
    return v;
}

// ---------------- cp.async helpers ----------------
__device__ __forceinline__ void cp16(void* smem_dst, const void* gsrc) {
    unsigned saddr = (unsigned)__cvta_generic_to_shared(smem_dst);
    asm volatile("cp.async.cg.shared.global [%0], [%1], 16;" :: "r"(saddr), "l"(gsrc));
}
__device__ __forceinline__ void cp_commit() { asm volatile("cp.async.commit_group;"); }
__device__ __forceinline__ void cp_wait0()  { asm volatile("cp.async.wait_group 0;"); }

// ---------------- bf16 split helpers ----------------
__device__ __forceinline__ void split2(float x, float y, unsigned& hi, unsigned& lo) {
    __nv_bfloat16 hx = __float2bfloat16(x);
    __nv_bfloat16 hy = __float2bfloat16(y);
    float rx = x - __bfloat162float(hx);
    float ry = y - __bfloat162float(hy);
    __nv_bfloat16 lx = __float2bfloat16(rx);
    __nv_bfloat16 ly = __float2bfloat16(ry);
    hi = (unsigned)__bfloat16_as_ushort(hx) | ((unsigned)__bfloat16_as_ushort(hy) << 16);
    lo = (unsigned)__bfloat16_as_ushort(lx) | ((unsigned)__bfloat16_as_ushort(ly) << 16);
}

// ---------------- split kernel: fp32 -> packed bf16 hi/lo ----------------
__global__ void split_kernel(const float* __restrict__ src,
                             unsigned* __restrict__ hi,
                             unsigned* __restrict__ lo, int n2) {
    int i = blockIdx.x * 256 + threadIdx.x;
    if (i >= n2) return;
    float2 v = ((const float2*)src)[i];
    unsigned h, l;
    split2(v.x, v.y, h, l);
    hi[i] = h; lo[i] = l;
}

// ---------------- 0. zero expert counters ----------------
__global__ void zero_cnt_kernel() {
    if (threadIdx.x < NEXP) g_cnt[threadIdx.x] = 0;
}

// ---------------- 1. routing ----------------
__global__ void routing_kernel(const float* __restrict__ x,
                               const float* __restrict__ cw,
                               const float* __restrict__ cb,
                               const float* __restrict__ wealth) {
    int t = blockIdx.x, tid = threadIdx.x;
    const float* xt = x + (size_t)t * HDIM;
    float acc[NEXP];
    #pragma unroll
    for (int e = 0; e < NEXP; e++) acc[e] = 0.f;
    for (int h = tid; h < HDIM; h += 256) {
        float xv = xt[h];
        #pragma unroll
        for (int e = 0; e < NEXP; e++) acc[e] += xv * cw[(size_t)e * HDIM + h];
    }
    __shared__ float part[8][NEXP];
    int warp = tid >> 5, lane = tid & 31;
    #pragma unroll
    for (int e = 0; e < NEXP; e++) acc[e] = warpsum(acc[e]);
    if (lane == 0) {
        #pragma unroll
        for (int e = 0; e < NEXP; e++) part[warp][e] = acc[e];
    }
    __syncthreads();
    if (tid == 0) {
        float bids[NEXP];
        #pragma unroll
        for (int e = 0; e < NEXP; e++) {
            float s = 0.f;
            #pragma unroll
            for (int w = 0; w < 8; w++) s += part[w][e];
            float conf = 1.f / (1.f + expf(-(s + cb[e])));
            bids[e] = conf * wealth[e];
        }
        int i0 = 0, i1 = -1;
        float b0 = bids[0], b1 = -1e30f;
        #pragma unroll
        for (int e = 1; e < NEXP; e++) {
            if (bids[e] > b0)      { b1 = b0; i1 = i0; b0 = bids[e]; i0 = e; }
            else if (bids[e] > b1) { b1 = bids[e]; i1 = e; }
        }
        float e1 = expf(b1 - b0);
        float inv = 1.f / (1.f + e1);
        g_w[t * 2 + 0] = inv;
        g_w[t * 2 + 1] = e1 * inv;
        int p0 = atomicAdd(&g_cnt[i0], 1); g_list[i0][p0] = t * 2 + 0;
        int p1 = atomicAdd(&g_cnt[i1], 1); g_list[i1][p1] = t * 2 + 1;
    }
}

// ---------------- 2. grouped LoRA-in, K-split ----------------
// grid (SLOTS/64, LK_CH, NEXP)
__global__ void __launch_bounds__(256) lora_in_grouped(const float* __restrict__ x,
                                                       const float* __restrict__ gA,
                                                       const float* __restrict__ uA) {
    int e = blockIdx.z, kc = blockIdx.y;
    int cnt = g_cnt[e];
    int base = blockIdx.x * 64;
    if (base >= cnt) return;
    __shared__ float xsT [16][64];
    __shared__ float gAsT[16][64];
    __shared__ float uAsT[16][64];
    __shared__ int sidx[64];
    int tid = threadIdx.x;
    if (tid < 64) sidx[tid] = (base + tid < cnt) ? g_list[e][base + tid] : -1;
    __syncthreads();

    int ld_row = tid >> 2;
    int ld_k   = (tid & 3) * 4;
    int s_ld = sidx[ld_row];
    int t_ld = (s_ld >= 0) ? (s_ld >> 1) : 0;
    const float* xp  = x  + (size_t)t_ld * HDIM + ld_k;
    const float* gAp = gA + ((size_t)e * RDIM + ld_row) * HDIM + ld_k;
    const float* uAp = uA + ((size_t)e * RDIM + ld_row) * HDIM + ld_k;

    int tx = tid & 15, ty = tid >> 4;
    float accg[4][4], accu[4][4];
    #pragma unroll
    for (int i = 0; i < 4; i++)
        #pragma unroll
        for (int j = 0; j < 4; j++) { accg[i][j] = 0.f; accu[i][j] = 0.f; }

    const int KC = HDIM / LK_CH;       // 512
    int kstart = kc * KC;
    for (int k0 = kstart; k0 < kstart + KC; k0 += 16) {
        float4 xv = *(const float4*)(xp + k0);
        float4 gv = *(const float4*)(gAp + k0);
        float4 uv = *(const float4*)(uAp + k0);
        xsT [ld_k + 0][ld_row] = xv.x; xsT [ld_k + 1][ld_row] = xv.y;
        xsT [ld_k + 2][ld_row] = xv.z; xsT [ld_k + 3][ld_row] = xv.w;
        gAsT[ld_k + 0][ld_row] = gv.x; gAsT[ld_k + 1][ld_row] = gv.y;
        gAsT[ld_k + 2][ld_row] = gv.z; gAsT[ld_k + 3][ld_row] = gv.w;
        uAsT[ld_k + 0][ld_row] = uv.x; uAsT[ld_k + 1][ld_row] = uv.y;
        uAsT[ld_k + 2][ld_row] = uv.z; uAsT[ld_k + 3][ld_row] = uv.w;
        __syncthreads();
        #pragma unroll
        for (int k = 0; k < 16; k++) {
            float a0 = xsT[k][ty * 4 + 0], a1 = xsT[k][ty * 4 + 1];
            float a2 = xsT[k][ty * 4 + 2], a3 = xsT[k][ty * 4 + 3];
            float4 gr = *(const float4*)&gAsT[k][tx * 4];
            float4 ur = *(const float4*)&uAsT[k][tx * 4];
            accg[0][0] += a0 * gr.x; accg[0][1] += a0 * gr.y; accg[0][2] += a0 * gr.z; accg[0][3] += a0 * gr.w;
            accg[1][0] += a1 * gr.x; accg[1][1] += a1 * gr.y; accg[1][2] += a1 * gr.z; accg[1][3] += a1 * gr.w;
            accg[2][0] += a2 * gr.x; accg[2][1] += a2 * gr.y; accg[2][2] += a2 * gr.z; accg[2][3] += a2 * gr.w;
            accg[3][0] += a3 * gr.x; accg[3][1] += a3 * gr.y; accg[3][2] += a3 * gr.z; accg[3][3] += a3 * gr.w;
            accu[0][0] += a0 * ur.x; accu[0][1] += a0 * ur.y; accu[0][2] += a0 * ur.z; accu[0][3] += a0 * ur.w;
            accu[1][0] += a1 * ur.x; accu[1][1] += a1 * ur.y; accu[1][2] += a1 * ur.z; accu[1][3] += a1 * ur.w;
            accu[2][0] += a2 * ur.x; accu[2][1] += a2 * ur.y; accu[2][2] += a2 * ur.z; accu[2][3] += a2 * ur.w;
            accu[3][0] += a3 * ur.x; accu[3][1] += a3 * ur.y; accu[3][2] += a3 * ur.z; accu[3][3] += a3 * ur.w;
        }
        __syncthreads();
    }
    size_t pbase = (size_t)kc * SLOTS * RDIM;
    #pragma unroll
    for (int tt = 0; tt < 4; tt++) {
        int s = sidx[ty * 4 + tt];
        if (s < 0) continue;
        *(float4*)&g_tgp[pbase + (size_t)s * RDIM + tx * 4] = make_float4(accg[tt][0], accg[tt][1], accg[tt][2], accg[tt][3]);
        *(float4*)&g_tup[pbase + (size_t)s * RDIM + tx * 4] = make_float4(accu[tt][0], accu[tt][1], accu[tt][2], accu[tt][3]);
    }
}

// ---------------- 2b. reduce lora partials (fixed order -> deterministic) ----------------
__global__ void lora_reduce_kernel() {
    int i = blockIdx.x * 256 + threadIdx.x;   // SLOTS*RDIM total
    float sg = 0.f, su = 0.f;
    #pragma unroll
    for (int c = 0; c < LK_CH; c++) {
        sg += g_tgp[(size_t)c * SLOTS * RDIM + i];
        su += g_tup[(size_t)c * SLOTS * RDIM + i];
    }
    g_tg[i] = sg; g_tu[i] = su;
}

// ---------------- bf16 mma helper ----------------
__device__ __forceinline__ void mma_bf16(float& c0, float& c1, float& c2, float& c3,
                                         unsigned a0, unsigned a1, unsigned a2, unsigned a3,
                                         unsigned b0, unsigned b1) {
    asm volatile(
        "mma.sync.aligned.m16n8k16.row.col.f32.bf16.bf16.f32 "
        "{%0,%1,%2,%3}, {%4,%5,%6,%7}, {%8,%9}, {%0,%1,%2,%3};\n"
        : "+f"(c0), "+f"(c1), "+f"(c2), "+f"(c3)
        : "r"(a0), "r"(a1), "r"(a2), "r"(a3), "r"(b0), "r"(b1));
}

// ---------------- bf16x2 3-pass GEMM: C[M,N] = A[M,K] @ B[N,K]^T ----------------
// Inputs are precomputed packed-bf16 hi/lo (K2 = K/2 u32 per row).
// BM=BN=128, BK=16 (8 u32), 256 threads, warp grid 2m x 4n, warp tile 64x32.
// smem: 4 mats x 2 buf x 128x12 u32 = 48KB exactly; [128][12] is bank-conflict-free.
__device__ __forceinline__ void gemm_bf16x2_body(const unsigned* __restrict__ Ahi,
                                                 const unsigned* __restrict__ Alo,
                                                 const unsigned* __restrict__ Bhi,
                                                 const unsigned* __restrict__ Blo,
                                                 float* __restrict__ C,
                                                 int N, int K2) {
    __shared__ unsigned As[2][2][128][12];   // [buf][hi/lo][row][u32 col]
    __shared__ unsigned Bs[2][2][128][12];

    int tid = threadIdx.x;
    int m0 = blockIdx.y * 128, n0 = blockIdx.x * 128;
    int warp = tid >> 5, lane = tid & 31;
    int wm = (warp & 1) * 64;
    int wn = (warp >> 1) * 32;
    int g = lane >> 2, tq = lane & 3;

    int lrow = tid >> 1;            // 0..127
    int lcol = (tid & 1) * 4;       // 0 or 4 (u32)
    const unsigned* Aph = Ahi + (size_t)(m0 + lrow) * K2 + lcol;
    const unsigned* Apl = Alo + (size_t)(m0 + lrow) * K2 + lcol;
    const unsigned* Bph = Bhi + (size_t)(n0 + lrow) * K2 + lcol;
    const unsigned* Bpl = Blo + (size_t)(n0 + lrow) * K2 + lcol;

    float acc[4][4][4];
    #pragma unroll
    for (int mi = 0; mi < 4; mi++)
        #pragma unroll
        for (int ni = 0; ni < 4; ni++)
            #pragma unroll
            for (int c = 0; c < 4; c++) acc[mi][ni][c] = 0.f;

    int nk = K2 >> 3;   // K/16 tiles

    cp16(&As[0][0][lrow][lcol], Aph);
    cp16(&As[0][1][lrow][lcol], Apl);
    cp16(&Bs[0][0][lrow][lcol], Bph);
    cp16(&Bs[0][1][lrow][lcol], Bpl);
    cp_commit(); cp_wait0();
    __syncthreads();

    for (int kt = 0; kt < nk; kt++) {
        int cur = kt & 1;
        if (kt + 1 < nk) {
            int nxt = cur ^ 1;
            int o = (kt + 1) << 3;
            cp16(&As[nxt][0][lrow][lcol], Aph + o);
            cp16(&As[nxt][1][lrow][lcol], Apl + o);
            cp16(&Bs[nxt][0][lrow][lcol], Bph + o);
            cp16(&Bs[nxt][1][lrow][lcol], Bpl + o);
            cp_commit();
        }
        unsigned ah[4][4], al[4][4];
        #pragma unroll
        for (int mi = 0; mi < 4; mi++) {
            int mb = wm + mi * 16;
            ah[mi][0] = As[cur][0][mb + g][tq];
            ah[mi][1] = As[cur][0][mb + g + 8][tq];
            ah[mi][2] = As[cur][0][mb + g][tq + 4];
            ah[mi][3] = As[cur][0][mb + g + 8][tq + 4];
            al[mi][0] = As[cur][1][mb + g][tq];
            al[mi][1] = As[cur][1][mb + g + 8][tq];
            al[mi][2] = As[cur][1][mb + g][tq + 4];
            al[mi][3] = As[cur][1][mb + g + 8][tq + 4];
        }
        unsigned bh[4][2], bl[4][2];
        #pragma unroll
        for (int ni = 0; ni < 4; ni++) {
            int nb = wn + ni * 8;
            bh[ni][0] = Bs[cur][0][nb + g][tq];
            bh[ni][1] = Bs[cur][0][nb + g][tq + 4];
            bl[ni][0] = Bs[cur][1][nb + g][tq];
            bl[ni][1] = Bs[cur][1][nb + g][tq + 4];
        }
        #pragma unroll
        for (int mi = 0; mi < 4; mi++)
            #pragma unroll
            for (int ni = 0; ni < 4; ni++) {
                float* c = acc[mi][ni];
                mma_bf16(c[0], c[1], c[2], c[3],
                         ah[mi][0], ah[mi][1], ah[mi][2], ah[mi][3],
                         bh[ni][0], bh[ni][1]);
                mma_bf16(c[0], c[1], c[2], c[3],
                         ah[mi][0], ah[mi][1], ah[mi][2], ah[mi][3],
                         bl[ni][0], bl[ni][1]);
                mma_bf16(c[0], c[1], c[2], c[3],
                         al[mi][0], al[mi][1], al[mi][2], al[mi][3],
                         bh[ni][0], bh[ni][1]);
            }
        cp_wait0();
        __syncthreads();
    }

    #pragma unroll
    for (int mi = 0; mi < 4; mi++) {
        int row0 = m0 + wm + mi * 16 + g;
        int row1 = row0 + 8;
        #pragma unroll
        for (int ni = 0; ni < 4; ni++) {
            int col = n0 + wn + ni * 8 + 2 * tq;
            float* c = acc[mi][ni];
            *(float2*)&C[(size_t)row0 * N + col] = make_float2(c[0], c[1]);
            *(float2*)&C[(size_t)row1 * N + col] = make_float2(c[2], c[3]);
        }
    }
}

// ---------------- 3. base gate/up GEMM ----------------
__global__ void __launch_bounds__(256, 1) sgemm_gateup() {
    const unsigned* Bh = blockIdx.z ? g_wuhi : g_wghi;
    const unsigned* Bl = blockIdx.z ? g_wulo : g_wglo;
    float* C = blockIdx.z ? g_base_up : g_base_gate;
    gemm_bf16x2_body(g_xhi, g_xlo, Bh, Bl, C, IDIM, HDIM / 2);
}

// ---------------- 4. grouped hid ----------------
__global__ void __launch_bounds__(256) hid_grouped(const float* __restrict__ gB,
                                                   const float* __restrict__ uB) {
    int e = blockIdx.y;
    int cnt = g_cnt[e];
    if (cnt == 0) return;
    int i0 = blockIdx.x * 64;
    __shared__ float gBsT[RDIM][64];
    __shared__ float uBsT[RDIM][64];
    __shared__ float tgsT[RDIM][32];
    __shared__ float tusT[RDIM][32];
    int tid = threadIdx.x;
    {
        int il = tid >> 2, rb = (tid & 3) * 4;
        const float* gp = gB + ((size_t)e * IDIM + i0 + il) * RDIM;
        const float* up = uB + ((size_t)e * IDIM + i0 + il) * RDIM;
        #pragma unroll
        for (int j = 0; j < 4; j++) {
            int r0 = rb + j * 16;
            float4 gv = *(const float4*)(gp + r0);
            float4 uv = *(const float4*)(up + r0);
            gBsT[r0 + 0][il] = gv.x; gBsT[r0 + 1][il] = gv.y; gBsT[r0 + 2][il] = gv.z; gBsT[r0 + 3][il] = gv.w;
            uBsT[r0 + 0][il] = uv.x; uBsT[r0 + 1][il] = uv.y; uBsT[r0 + 2][il] = uv.z; uBsT[r0 + 3][il] = uv.w;
        }
    }
    __syncthreads();

    int tx = tid & 15, ty = tid >> 4;
    int tl_ld = tid >> 3;
    int rb_ld = (tid & 7) * 8;

    for (int c0 = 0; c0 < cnt; c0 += 32) {
        int s_ld = (c0 + tl_ld < cnt) ? g_list[e][c0 + tl_ld] : 0;
        #pragma unroll
        for (int h = 0; h < 2; h++) {
            int r0 = rb_ld + h * 4;
            float4 gv = *(const float4*)&g_tg[(size_t)s_ld * RDIM + r0];
            float4 uv = *(const float4*)&g_tu[(size_t)s_ld * RDIM + r0];
            tgsT[r0 + 0][tl_ld] = gv.x; tgsT[r0 + 1][tl_ld] = gv.y; tgsT[r0 + 2][tl_ld] = gv.z; tgsT[r0 + 3][tl_ld] = gv.w;
            tusT[r0 + 0][tl_ld] = uv.x; tusT[r0 + 1][tl_ld] = uv.y; tusT[r0 + 2][tl_ld] = uv.z; tusT[r0 + 3][tl_ld] = uv.w;
        }
        __syncthreads();

        float accg[2][4], accu[2][4];
        #pragma unroll
        for (int i = 0; i < 2; i++)
            #pragma unroll
            for (int j = 0; j < 4; j++) { accg[i][j] = 0.f; accu[i][j] = 0.f; }
        #pragma unroll
        for (int r = 0; r < RDIM; r++) {
            float g0 = tgsT[r][ty * 2 + 0], g1 = tgsT[r][ty * 2 + 1];
            float u0 = tusT[r][ty * 2 + 0], u1 = tusT[r][ty * 2 + 1];
            float4 gb = *(const float4*)&gBsT[r][tx * 4];
            float4 ub = *(const float4*)&uBsT[r][tx * 4];
            accg[0][0] += g0 * gb.x; accg[0][1] += g0 * gb.y; accg[0][2] += g0 * gb.z; accg[0][3] += g0 * gb.w;
            accg[1][0] += g1 * gb.x; accg[1][1] += g1 * gb.y; accg[1][2] += g1 * gb.z; accg[1][3] += g1 * gb.w;
            accu[0][0] += u0 * ub.x; accu[0][1] += u0 * ub.y; accu[0][2] += u0 * ub.z; accu[0][3] += u0 * ub.w;
            accu[1][0] += u1 * ub.x; accu[1][1] += u1 * ub.y; accu[1][2] += u1 * ub.z; accu[1][3] += u1 * ub.w;
        }
        #pragma unroll
        for (int tt = 0; tt < 2; tt++) {
            int tl = ty * 2 + tt;
            if (c0 + tl >= cnt) continue;
            int s = g_list[e][c0 + tl];
            int t = s >> 1;
            size_t boff = (size_t)t * IDIM + i0 + tx * 4;
            float4 bg = *(const float4*)&g_base_gate[boff];
            float4 bu = *(const float4*)&g_base_up[boff];
            float gte[4] = {bg.x + SCALE * accg[tt][0], bg.y + SCALE * accg[tt][1],
                            bg.z + SCALE * accg[tt][2], bg.w + SCALE * accg[tt][3]};
            float upe[4] = {bu.x + SCALE * accu[tt][0], bu.y + SCALE * accu[tt][1],
                            bu.z + SCALE * accu[tt][2], bu.w + SCALE * accu[tt][3]};
            float4 hv;
            hv.x = gte[0] / (1.f + expf(-gte[0])) * upe[0];
            hv.y = gte[1] / (1.f + expf(-gte[1])) * upe[1];
            hv.z = gte[2] / (1.f + expf(-gte[2])) * upe[2];
            hv.w = gte[3] / (1.f + expf(-gte[3])) * upe[3];
            *(float4*)&g_hid[(size_t)s * IDIM + i0 + tx * 4] = hv;
        }
        __syncthreads();
    }
}

// ---------------- 5. hbar + split fused: hbhi/hblo = split(w0*hid0 + w1*hid1) ----------------
__global__ void hbar_split_kernel() {
    int t = blockIdx.x, tid = threadIdx.x;
    float w0 = g_w[t * 2], w1 = g_w[t * 2 + 1];
    const float2* h0 = (const float2*)(g_hid + (size_t)(t * 2) * IDIM);
    const float2* h1 = (const float2*)(g_hid + (size_t)(t * 2 + 1) * IDIM);
    unsigned* ph = g_hbhi + (size_t)t * (IDIM / 2);
    unsigned* pl = g_hblo + (size_t)t * (IDIM / 2);
    for (int j = tid; j < IDIM / 2; j += 256) {
        float2 a = h0[j];
        float2 b = h1[j];
        float v0 = w0 * a.x + w1 * b.x;
        float v1 = w0 * a.y + w1 * b.y;
        unsigned hi, lo;
        split2(v0, v1, hi, lo);
        ph[j] = hi; pl[j] = lo;
    }
}

// ---------------- 6. grouped td, K-split ----------------
// grid (SLOTS/64, TD_CH, NEXP)
__global__ void __launch_bounds__(256) td_grouped(const float* __restrict__ dA) {
    int e = blockIdx.z, kc = blockIdx.y;
    int cnt = g_cnt[e];
    int base = blockIdx.x * 64;
    if (base >= cnt) return;
    __shared__ float hidT[32][64];
    __shared__ float dAT [32][64];
    __shared__ int sidx[64];
    int tid = threadIdx.x;
    if (tid < 64) sidx[tid] = (base + tid < cnt) ? g_list[e][base + tid] : -1;
    __syncthreads();

    int rl = tid >> 2;
    int ib = (tid & 3) * 8;
    int s_ld = sidx[rl];
    const float* hp = g_hid + (size_t)(s_ld >= 0 ? s_ld : 0) * IDIM + ib;
    const float* dp = dA + ((size_t)e * RDIM + rl) * IDIM + ib;

    int tx = tid & 15, ty = tid >> 4;
    float acc[4][4];
    #pragma unroll
    for (int i = 0; i < 4; i++)
        #pragma unroll
        for (int j = 0; j < 4; j++) acc[i][j] = 0.f;

    const int KC = IDIM / TD_CH;      // 896
    int kstart = kc * KC;
    for (int k0 = kstart; k0 < kstart + KC; k0 += 32) {
        #pragma unroll
        for (int h = 0; h < 2; h++) {
            int i1 = ib + h * 4;
            float4 hv = *(const float4*)(hp + k0 + h * 4);
            float4 dv = *(const float4*)(dp + k0 + h * 4);
            hidT[i1 + 0][rl] = hv.x; hidT[i1 + 1][rl] = hv.y; hidT[i1 + 2][rl] = hv.z; hidT[i1 + 3][rl] = hv.w;
            dAT [i1 + 0][rl] = dv.x; dAT [i1 + 1][rl] = dv.y; dAT [i1 + 2][rl] = dv.z; dAT [i1 + 3][rl] = dv.w;
        }
        __syncthreads();
        #pragma unroll
        for (int i = 0; i < 32; i++) {
            float a0 = hidT[i][ty * 4 + 0], a1 = hidT[i][ty * 4 + 1];
            float a2 = hidT[i][ty * 4 + 2], a3 = hidT[i][ty * 4 + 3];
            float4 d = *(const float4*)&dAT[i][tx * 4];
            acc[0][0] += a0 * d.x; acc[0][1] += a0 * d.y; acc[0][2] += a0 * d.z; acc[0][3] += a0 * d.w;
            acc[1][0] += a1 * d.x; acc[1][1] += a1 * d.y; acc[1][2] += a1 * d.z; acc[1][3] += a1 * d.w;
            acc[2][0] += a2 * d.x; acc[2][1] += a2 * d.y; acc[2][2] += a2 * d.z; acc[2][3] += a2 * d.w;
            acc[3][0] += a3 * d.x; acc[3][1] += a3 * d.y; acc[3][2] += a3 * d.z; acc[3][3] += a3 * d.w;
        }
        __syncthreads();
    }
    size_t pbase = (size_t)kc * SLOTS * RDIM;
    #pragma unroll
    for (int tt = 0; tt < 4; tt++) {
        int s = sidx[ty * 4 + tt];
        if (s < 0) continue;
        *(float4*)&g_tdp[pbase + (size_t)s * RDIM + tx * 4] =
            make_float4(acc[tt][0], acc[tt][1], acc[tt][2], acc[tt][3]);
    }
}

// ---------------- 6b. reduce td partials ----------------
__global__ void td_reduce_kernel() {
    int i = blockIdx.x * 256 + threadIdx.x;   // SLOTS*RDIM
    int s = i >> 6;
    float v = 0.f;
    #pragma unroll
    for (int c = 0; c < TD_CH; c++) v += g_tdp[(size_t)c * SLOTS * RDIM + i];
    g_tdw[i] = v * g_w[s] * SCALE;
}

// ---------------- 7. out = hbar @ D^T ----------------
__global__ void __launch_bounds__(256, 1) sgemm_down(float* __restrict__ out) {
    gemm_bf16x2_body(g_hbhi, g_hblo, g_wdhi, g_wdlo, out, HDIM, IDIM / 2);
}

// ---------------- 8. grouped down-LoRA ----------------
__global__ void __launch_bounds__(256) downlora_grouped(const float* __restrict__ dB) {
    int e = blockIdx.y;
    int cnt = g_cnt[e];
    if (cnt == 0) return;
    int h0 = blockIdx.x * 64;
    __shared__ float dBT[RDIM][64];
    __shared__ float tdT[RDIM][64];
    __shared__ int sidx[64];
    int tid = threadIdx.x;
    {
        int hl = tid >> 2, rb = (tid & 3) * 4;
        const float* dp = dB + ((size_t)e * HDIM + h0 + hl) * RDIM;
        #pragma unroll
        for (int j = 0; j < 4; j++) {
            int r0 = rb + j * 16;
            float4 v = *(const float4*)(dp + r0);
            dBT[r0 + 0][hl] = v.x; dBT[r0 + 1][hl] = v.y; dBT[r0 + 2][hl] = v.z; dBT[r0 + 3][hl] = v.w;
        }
    }
    __syncthreads();

    int tx = tid & 15, ty = tid >> 4;
    int tl_ld = tid >> 2, rb_ld = (tid & 3) * 4;

    for (int c0 = 0; c0 < cnt; c0 += 64) {
        if (tid < 64) sidx[tid] = (c0 + tid < cnt) ? g_list[e][c0 + tid] : -1;
        __syncthreads();
        int s_ld = sidx[tl_ld];
        const float* tp = g_tdw + (size_t)(s_ld >= 0 ? s_ld : 0) * RDIM;
        #pragma unroll
        for (int j = 0; j < 4; j++) {
            int r0 = rb_ld + j * 16;
            float4 v = *(const float4*)(tp + r0);
            tdT[r0 + 0][tl_ld] = v.x; tdT[r0 + 1][tl_ld] = v.y; tdT[r0 + 2][tl_ld] = v.z; tdT[r0 + 3][tl_ld] = v.w;
        }
        __syncthreads();

        float acc[4][4];
        #pragma unroll
        for (int i = 0; i < 4; i++)
            #pragma unroll
            for (int j = 0; j < 4; j++) acc[i][j] = 0.f;
        #pragma unroll
        for (int r = 0; r < RDIM; r++) {
            float a0 = tdT[r][ty * 4 + 0], a1 = tdT[r][ty * 4 + 1];
            float a2 = tdT[r][ty * 4 + 2], a3 = tdT[r][ty * 4 + 3];
            float4 b = *(const float4*)&dBT[r][tx * 4];
            acc[0][0] += a0 * b.x; acc[0][1] += a0 * b.y; acc[0][2] += a0 * b.z; acc[0][3] += a0 * b.w;
            acc[1][0] += a1 * b.x; acc[1][1] += a1 * b.y; acc[1][2] += a1 * b.z; acc[1][3] += a1 * b.w;
            acc[2][0] += a2 * b.x; acc[2][1] += a2 * b.y; acc[2][2] += a2 * b.z; acc[2][3] += a2 * b.w;
            acc[3][0] += a3 * b.x; acc[3][1] += a3 * b.y; acc[3][2] += a3 * b.z; acc[3][3] += a3 * b.w;
        }
        #pragma unroll
        for (int tt = 0; tt < 4; tt++) {
            int s = sidx[ty * 4 + tt];
            if (s < 0) continue;
            *(float4*)&g_dl[(size_t)s * HDIM + h0 + tx * 4] =
                make_float4(acc[tt][0], acc[tt][1], acc[tt][2], acc[tt][3]);
        }
        __syncthreads();
    }
}

// ---------------- 9. combine ----------------
__global__ void combine_kernel(float* __restrict__ out) {
    int t = blockIdx.x, tid = threadIdx.x;
    const float* d0 = g_dl + (size_t)(t * 2) * HDIM;
    const float* d1 = g_dl + (size_t)(t * 2 + 1) * HDIM;
    float* op = out + (size_t)t * HDIM;
    for (int h = tid * 4; h < HDIM; h += 1024) {
        float4 o = *(const float4*)(op + h);
        float4 a = *(const float4*)(d0 + h);
        float4 b = *(const float4*)(d1 + h);
        *(float4*)(op + h) = make_float4(o.x + a.x + b.x, o.y + a.y + b.y,
                                         o.z + a.z + b.z, o.w + a.w + b.w);
    }
}

// ---------------- launch ----------------
extern "C" void kernel_launch(void* const* d_in, const int* in_sizes, int n_in,
                              void* d_out, int out_size) {
    const float* x      = (const float*)d_in[0];
    const float* conf_w = (const float*)d_in[1];
    const float* conf_b = (const float*)d_in[2];
    const float* wealth = (const float*)d_in[3];
    const float* bgw    = (const float*)d_in[4];
    const float* buw    = (const float*)d_in[5];
    const float* bdw    = (const float*)d_in[6];
    const float* gA     = (const float*)d_in[7];
    const float* gB     = (const float*)d_in[8];
    const float* uA     = (const float*)d_in[9];
    const float* uB     = (const float*)d_in[10];
    const float* dA     = (const float*)d_in[11];
    const float* dB     = (const float*)d_in[12];
    float* out = (float*)d_out;

    const int n2_x = T_TOK * HDIM / 2;
    const int n2_w = IDIM * HDIM / 2;

    zero_cnt_kernel<<<1, 32>>>();
    // resolve device addresses of split targets
    unsigned *xhi, *xlo, *wghi, *wglo, *wuhi, *wulo, *wdhi, *wdlo;
    cudaGetSymbolAddress((void**)&xhi, g_xhi);   cudaGetSymbolAddress((void**)&xlo, g_xlo);
    cudaGetSymbolAddress((void**)&wghi, g_wghi); cudaGetSymbolAddress((void**)&wglo, g_wglo);
    cudaGetSymbolAddress((void**)&wuhi, g_wuhi); cudaGetSymbolAddress((void**)&wulo, g_wulo);
    cudaGetSymbolAddress((void**)&wdhi, g_wdhi); cudaGetSymbolAddress((void**)&wdlo, g_wdlo);

    split_kernel<<<(n2_x + 255) / 256, 256>>>(x,   xhi,  xlo,  n2_x);
    split_kernel<<<(n2_w + 255) / 256, 256>>>(bgw, wghi, wglo, n2_w);
    split_kernel<<<(n2_w + 255) / 256, 256>>>(buw, wuhi, wulo, n2_w);
    split_kernel<<<(n2_w + 255) / 256, 256>>>(bdw, wdhi, wdlo, n2_w);

    routing_kernel<<<T_TOK, 256>>>(x, conf_w, conf_b, wealth);
    sgemm_gateup<<<dim3(IDIM / 128, T_TOK / 128, 2), 256>>>();
    lora_in_grouped<<<dim3(SLOTS / 64, LK_CH, NEXP), 256>>>(x, gA, uA);
    lora_reduce_kernel<<<SLOTS * RDIM / 256, 256>>>();
    hid_grouped<<<dim3(IDIM / 64, NEXP), 256>>>(gB, uB);
    hbar_split_kernel<<<T_TOK, 256>>>();
    td_grouped<<<dim3(SLOTS / 64, TD_CH, NEXP), 256>>>(dA);
    td_reduce_kernel<<<SLOTS * RDIM / 256, 256>>>();
    sgemm_down<<<dim3(HDIM / 128, T_TOK / 128), 256>>>(out);
    downlora_grouped<<<dim3(HDIM / 64, NEXP), 256>>>(dB);
    combine_kernel<<<T_TOK, 256>>>(out);
}